// round 11
// baseline (speedup 1.0000x reference)
#include <cuda_runtime.h>

// DynamicUpsamplingFilter (u-split CTAs: half-size scheduling quantum,
// per-thread behavior identical to the 63.2us R8/R9 kernel):
//   x:       (4, 3, 180, 320) f32
//   filters: (4, 25, 16, 180, 320) f32
//   out:     (4, 48, 180, 320) f32
//   out[n, c*16+u, h, w] = sum_p x_pad[n, c, h+p/5-2, w+p%5-2] * filters[n, p, u, h, w]

#define NN 4
#define CC 3
#define HH 180
#define WW 320
#define UU 16
#define KH 5
#define KW 5
#define PP (KH*KW)
#define TILE_W 64
#define SROW 68                 // TILE_W + 4 halo
#define XELEMS (CC * KH * SROW) // 1020 smem elements
#define WT (WW / TILE_W)        // 5

__global__ void __launch_bounds__(128, 10)
duf_kernel(const float* __restrict__ x,
           const float* __restrict__ filters,
           float* __restrict__ out) {
    // Block: one (n, h, w-tile of 64, u-half). 128 threads = 8 u x 16 w-quads.
    __shared__ float sx[CC][KH][SROW];  // 4080 B

    const int wq = threadIdx.x & 15;
    const int u  = (threadIdx.x >> 4) + ((blockIdx.x & 1) << 3);  // 0..15
    const int wb = (blockIdx.x >> 1) * TILE_W;
    const int h  = blockIdx.y;
    const int n  = blockIdx.z;

    const int w0 = wb + wq * 4;
    const float* fp = filters + ((((size_t)n * PP) * UU + u) * HH + h) * WW + w0;
    const size_t PS = (size_t)UU * HH * WW;  // p-plane stride (elements)

    // ---- (1) x-tile loads FIRST (L2 hits sit ahead of the filter DRAM
    //      misses in the L1tex FIFO -> barrier releases on x latency)
    float xv[8];
    #pragma unroll
    for (int k = 0; k < 8; ++k) {
        const int e = threadIdx.x + k * 128;
        float v = 0.0f;
        if (e < XELEMS) {
            const int pos = e % SROW;
            const int t   = e / SROW;
            const int i   = t % KH;
            const int c   = t / KH;
            const int col = wb + pos - 2;
            const int row = h + i - 2;
            if ((unsigned)col < WW && (unsigned)row < HH)
                v = x[((n * CC + c) * HH + row) * WW + col];
        }
        xv[k] = v;
    }

    // ---- (2) hoist filter row 0 (DRAM stream in flight during fill)
    float4 cur[KW];
    #pragma unroll
    for (int j = 0; j < KW; ++j)
        cur[j] = __ldcs(reinterpret_cast<const float4*>(fp + (size_t)j * PS));

    // ---- (3) store x tile + barrier (waits only on the x loads)
    float* sflat = &sx[0][0][0];
    #pragma unroll
    for (int k = 0; k < 8; ++k) {
        const int e = threadIdx.x + k * 128;
        if (e < XELEMS) sflat[e] = xv[k];
    }
    __syncthreads();

    float4 acc[CC];
    #pragma unroll
    for (int c = 0; c < CC; ++c) acc[c] = make_float4(0.f, 0.f, 0.f, 0.f);

    // ---- (4) rolling pipeline: consume tap j, immediately refill slot j
    //      with row i+1's tap j (smooth load injection, single buffer)
    #pragma unroll
    for (int i = 0; i < KH; ++i) {
        float4 win[CC];
        #pragma unroll
        for (int c = 0; c < CC; ++c)
            win[c] = *reinterpret_cast<const float4*>(&sx[c][i][wq * 4]);

        #pragma unroll
        for (int j = 0; j < KW; ++j) {
            #pragma unroll
            for (int c = 0; c < CC; ++c) {
                acc[c].x = fmaf(win[c].x, cur[j].x, acc[c].x);
                acc[c].y = fmaf(win[c].y, cur[j].y, acc[c].y);
                acc[c].z = fmaf(win[c].z, cur[j].z, acc[c].z);
                acc[c].w = fmaf(win[c].w, cur[j].w, acc[c].w);
            }
            if (i < KH - 1)
                cur[j] = __ldcs(reinterpret_cast<const float4*>(
                    fp + (size_t)((i + 1) * KW + j) * PS));
            if (j < KW - 1) {
                #pragma unroll
                for (int c = 0; c < CC; ++c) {
                    const float nw = sx[c][i][wq * 4 + j + 4];
                    win[c] = make_float4(win[c].y, win[c].z, win[c].w, nw);
                }
            }
        }
    }

    // ---- store: out[n, c*16+u, h, w0..w0+3] ----
    #pragma unroll
    for (int c = 0; c < CC; ++c) {
        float4* optr = reinterpret_cast<float4*>(
            out + ((((size_t)n * (CC * UU)) + c * UU + u) * HH + h) * WW + w0);
        __stcs(optr, acc[c]);
    }
}

extern "C" void kernel_launch(void* const* d_in, const int* in_sizes, int n_in,
                              void* d_out, int out_size) {
    const float* x       = (const float*)d_in[0];
    const float* filters = (const float*)d_in[1];
    float* out           = (float*)d_out;

    dim3 grid(WT * 2, HH, NN);  // (10, 180, 4) = 7200 blocks
    dim3 block(128);
    duf_kernel<<<grid, block>>>(x, filters, out);
}